// round 14
// baseline (speedup 1.0000x reference)
#include <cuda_runtime.h>
#include <cuda_fp16.h>
#include <cstdint>
#include <cstddef>

#define Bb 8
#define Cc 768
#define Nn 4096
#define TOK (Bb*Nn)
#define BCN (Bb*Cc*Nn)   // 25165824

typedef unsigned long long ull;

// ---------------- scratch (static device globals) ---------------------------------
__device__ __align__(16) float  g_xx  [BCN];              // channel-major (B,C,N)
__device__ __align__(16) __half g_xxxh[BCN];              // fp16 (mma operand only)
__device__ __align__(16) __half g_th  [Bb*384*Nn];        // t, fp16
__device__ __align__(16) __half g_x5h [5u*(size_t)BCN];   // s: 0=xw 1=xk 2=xv 3=xr 4=xg
__device__ __align__(16) __half g_gateh[BCN];
__device__ __align__(16) __half g_hh  [(size_t)Bb*128*Nn];// decay hidden fp16 (padded)
__device__ __align__(16) float  g_r   [BCN];              // conv outputs fp32 (b,c,n)
__device__ __align__(16) float  g_k   [BCN];
__device__ __align__(16) float  g_v   [BCN];
__device__ __align__(16) float  g_dec [BCN];
__device__ __align__(16) float  g_y   [BCN];              // scan out (b,n,c)
__device__ __align__(16) __half g_y2h [BCN];              // normalized+gated (b,c,n)
// fp16 fragment-packed weights: [z][kt][mfr][lane][4] uint32 (half2)
__device__ __align__(16) uint32_t g_wh_t  [48*24*128];
__device__ __align__(16) uint32_t g_wh_w2 [5*4*48*128];
__device__ __align__(16) uint32_t g_wh_r  [2*24*24*128];
__device__ __align__(16) uint32_t g_wh_k  [2*24*24*128];
__device__ __align__(16) uint32_t g_wh_v  [2*24*24*128];
__device__ __align__(16) uint32_t g_wh_g  [2*24*24*128];
__device__ __align__(16) uint32_t g_wh_o  [2*24*24*128];
__device__ __align__(16) uint32_t g_wh_td1[48*8*128];
__device__ __align__(16) uint32_t g_wh_td2[4*48*128];

// ---------------- asm helpers ------------------------------------------------------
__device__ __forceinline__ uint32_t s2u(const void* p) {
    uint32_t a;
    asm("{ .reg .u64 t; cvta.to.shared.u64 t, %1; cvt.u32.u64 %0, t; }" : "=r"(a) : "l"(p));
    return a;
}
__device__ __forceinline__ void mma16(float* d, const uint4& a, uint32_t b0, uint32_t b1) {
    asm volatile("mma.sync.aligned.m16n8k16.row.col.f32.f16.f16.f32 "
        "{%0,%1,%2,%3}, {%4,%5,%6,%7}, {%8,%9}, {%0,%1,%2,%3};"
        : "+f"(d[0]), "+f"(d[1]), "+f"(d[2]), "+f"(d[3])
        : "r"(a.x), "r"(a.y), "r"(a.z), "r"(a.w), "r"(b0), "r"(b1));
}
__device__ __forceinline__ void ldmB(uint32_t& b0, uint32_t& b1, uint32_t addr) {
    asm volatile("ldmatrix.sync.aligned.m8n8.x2.trans.shared.b16 {%0,%1}, [%2];"
        : "=r"(b0), "=r"(b1) : "r"(addr));
}
// packed f32x2 ops (sm_103a)
__device__ __forceinline__ ull pk2(float lo, float hi) {
    ull d; asm("mov.b64 %0, {%1, %2};" : "=l"(d) : "f"(lo), "f"(hi)); return d;
}
__device__ __forceinline__ void upk2(float& lo, float& hi, ull v) {
    asm("mov.b64 {%0, %1}, %2;" : "=f"(lo), "=f"(hi) : "l"(v));
}
__device__ __forceinline__ ull mul2(ull a, ull b) {
    ull d; asm("mul.rn.f32x2 %0, %1, %2;" : "=l"(d) : "l"(a), "l"(b)); return d;
}
__device__ __forceinline__ ull fma2(ull a, ull b, ull c) {
    ull d; asm("fma.rn.f32x2 %0, %1, %2, %3;" : "=l"(d) : "l"(a), "l"(b), "l"(c)); return d;
}

// ---------------- K0: merged weight prep (one launch, table dispatch) --------------
__device__ __forceinline__ void pack_one(const float* __restrict__ src,
                                         uint32_t* __restrict__ dst,
                                         int M, int Mp, int K, int trans, size_t idx) {
    int KT = K >> 4, MFR = Mp >> 4;
    size_t per_z = (size_t)KT * MFR * 128;
    int z = (int)(idx / per_z);
    size_t rem = idx - (size_t)z * per_z;
    int kt  = (int)(rem / (MFR * 128));
    int r2  = (int)(rem % (MFR * 128));
    int mfr = r2 >> 7;
    int li  = r2 & 127;
    int lane = li >> 2, r = li & 3;
    int m = mfr * 16 + (lane >> 2) + ((r & 1) << 3);
    int k = kt * 16 + (lane & 3) * 2 + ((r >> 1) << 3);
    float f0 = 0.f, f1 = 0.f;
    if (m < M) {
        const float* sz = src + (size_t)z * M * K;
        if (trans) { f0 = sz[(size_t)k * M + m]; f1 = sz[(size_t)(k + 1) * M + m]; }
        else       { f0 = sz[(size_t)m * K + k]; f1 = sz[(size_t)m * K + k + 1]; }
    }
    __half2 h = __floats2half2_rn(f0, f1);
    dst[idx] = *(uint32_t*)&h;
}

__global__ void prep_all(const float* s_t, const float* s_w2, const float* s_r,
                         const float* s_k, const float* s_v, const float* s_g,
                         const float* s_o, const float* s_td1, const float* s_td2) {
    size_t idx = (size_t)blockIdx.x * 256 + threadIdx.x;
    if (idx < 147456)        pack_one(s_t,   g_wh_t,   320, 384, 768, 0, idx);
    else if (idx < 270336)   pack_one(s_w2,  g_wh_w2,  768, 768,  64, 1, idx - 147456);
    else if (idx < 417792)   pack_one(s_r,   g_wh_r,   384, 384, 384, 0, idx - 270336);
    else if (idx < 565248)   pack_one(s_k,   g_wh_k,   384, 384, 384, 0, idx - 417792);
    else if (idx < 712704)   pack_one(s_v,   g_wh_v,   384, 384, 384, 0, idx - 565248);
    else if (idx < 860160)   pack_one(s_g,   g_wh_g,   384, 384, 384, 0, idx - 712704);
    else if (idx < 1007616)  pack_one(s_o,   g_wh_o,   384, 384, 384, 0, idx - 860160);
    else if (idx < 1056768)  pack_one(s_td1, g_wh_td1,  64, 128, 768, 0, idx - 1007616);
    else if (idx < 1081344)  pack_one(s_td2, g_wh_td2, 768, 768,  64, 0, idx - 1056768);
}

// ---------------- K1: q_shift + xx(fp32) + xxx(fp16) -------------------------------
__global__ void shift_kernel(const float* __restrict__ x, const float* __restrict__ maa_x) {
    size_t idx = (size_t)blockIdx.x * 256 + threadIdx.x;
    if (idx >= (size_t)BCN) return;
    int n = (int)(idx & (Nn - 1));
    int c = (int)((idx >> 12) % Cc);
    int w = n & 63, hh = n >> 6;
    float xv = x[idx], s;
    int mode = c / 192;
    if (mode == 0)      s = (w  > 0 ) ? x[idx - 1 ] : 0.f;
    else if (mode == 1) s = (w  < 63) ? x[idx + 1 ] : 0.f;
    else if (mode == 2) s = (hh > 0 ) ? x[idx - 64] : 0.f;
    else                s = (hh < 63) ? x[idx + 64] : 0.f;
    float d = s - xv;
    g_xx[idx]   = d;
    g_xxxh[idx] = __float2half(fmaf(d, maa_x[c], xv));
}

// ---------------- fp16 tensor-core GEMM (single barrier per k-tile) ----------------
template<int ACT, int OUT>
__global__ void __launch_bounds__(256) gemm_h(
    const uint32_t* __restrict__ Wp, const __half* __restrict__ X,
    void* __restrict__ Yv, int Mp, int K, int wmod,
    long long sXz, long long sYz,
    const float* __restrict__ extra, const float* __restrict__ xin,
    const float* __restrict__ q0, const float* __restrict__ q1,
    const float* __restrict__ q2, const float* __restrict__ q3,
    const float* __restrict__ q4)
{
    const int z   = blockIdx.z;
    const int m0g = blockIdx.y * 128;
    const int n0g = blockIdx.x * 128;
    const int KT = K >> 4, MFR = Mp >> 4;

    const uint32_t* Wz;
    const __half* Xz;
    float* Yzf = nullptr; __half* Yzh = nullptr;
    const float* maa = nullptr; const float* xb = nullptr; const float* xxb = nullptr;
    if (ACT == 4) {
        int s = z % 5, b = z / 5;
        Wz = Wp + (size_t)s * KT * MFR * 128;
        Xz = X + (size_t)b * 384 * Nn + (size_t)s * 64 * Nn;
        Yzh = (__half*)Yv + (size_t)(s * 8 + b) * sYz;
        maa = (s==0)?q0:(s==1)?q1:(s==2)?q2:(s==3)?q3:q4;
        xb  = xin + (size_t)b * Cc * Nn;
        xxb = g_xx + (size_t)b * Cc * Nn;
    } else {
        Wz = Wp + (size_t)(z % wmod) * KT * MFR * 128;
        Xz = X + (size_t)z * sXz;
        if (OUT == 0) Yzf = (float*)Yv + (size_t)z * sYz;
        else          Yzh = (__half*)Yv + (size_t)z * sYz;
    }

    __shared__ __align__(16) __half Bs[2][16][136];

    const int t = threadIdx.x;
    const int lane = t & 31, wid = t >> 5;
    const int wm = wid >> 2, wn = wid & 3;
    const int kRow = t >> 4, c8 = (t & 15) * 8;

    float acc[4][4][4];
    #pragma unroll
    for (int i = 0; i < 4; i++)
        #pragma unroll
        for (int jx = 0; jx < 4; jx++)
            #pragma unroll
            for (int q = 0; q < 4; q++) acc[i][jx][q] = 0.f;

    uint4 aR[2][4];
    uint4 bRh;

    // prologue: tile 0 -> regs -> Bs[0], one barrier
    #pragma unroll
    for (int mf = 0; mf < 4; mf++) {
        int mfr = (m0g >> 4) + wm * 4 + mf;
        aR[0][mf] = *(const uint4*)&Wz[(((size_t)0 * MFR + mfr) * 32 + lane) * 4];
    }
    bRh = *(const uint4*)&Xz[(size_t)kRow * Nn + n0g + c8];
    *(uint4*)&Bs[0][kRow][c8] = bRh;
    __syncthreads();

    for (int kt = 0; kt < KT; kt++) {
        const int buf = kt & 1;
        const bool more = (kt + 1 < KT);
        if (more) {
            #pragma unroll
            for (int mf = 0; mf < 4; mf++) {
                int mfr = (m0g >> 4) + wm * 4 + mf;
                aR[buf ^ 1][mf] =
                    *(const uint4*)&Wz[(((size_t)(kt + 1) * MFR + mfr) * 32 + lane) * 4];
            }
            bRh = *(const uint4*)&Xz[(size_t)((kt + 1) * 16 + kRow) * Nn + n0g + c8];
        }
        // compute current buffer
        uint32_t base = s2u(&Bs[buf][lane & 15][wn * 32]);
        uint32_t bf[4][2];
        #pragma unroll
        for (int nf = 0; nf < 4; nf++) ldmB(bf[nf][0], bf[nf][1], base + nf * 16);
        #pragma unroll
        for (int mf = 0; mf < 4; mf++)
            #pragma unroll
            for (int nf = 0; nf < 4; nf++)
                mma16(acc[mf][nf], aR[buf][mf], bf[nf][0], bf[nf][1]);
        // stage next tile, single barrier
        if (more) {
            *(uint4*)&Bs[buf ^ 1][kRow][c8] = bRh;
            __syncthreads();
        }
    }

    // epilogue
    #pragma unroll
    for (int mf = 0; mf < 4; mf++) {
        int rr0 = m0g + wm * 64 + mf * 16 + (lane >> 2);
        #pragma unroll
        for (int hf = 0; hf < 2; hf++) {
            int rr = rr0 + hf * 8;
            float e  = (ACT == 3) ? extra[rr] : 0.f;
            float mc = (ACT == 4) ? maa[rr]   : 0.f;
            #pragma unroll
            for (int nf = 0; nf < 4; nf++) {
                int nc = n0g + wn * 32 + nf * 8 + (lane & 3) * 2;
                float v0 = acc[mf][nf][hf * 2 + 0];
                float v1 = acc[mf][nf][hf * 2 + 1];
                size_t off = (size_t)rr * Nn + nc;
                if (ACT == 1) { v0 = tanhf(v0); v1 = tanhf(v1); }
                else if (ACT == 2) { v0 = v0 / (1.f + expf(-v0)); v1 = v1 / (1.f + expf(-v1)); }
                else if (ACT == 3) { v0 = expf(-expf(e + v0)); v1 = expf(-expf(e + v1)); }
                else if (ACT == 4) {
                    float2 xv  = *(const float2*)&xb[off];
                    float2 xxv = *(const float2*)&xxb[off];
                    v0 = fmaf(xxv.x, mc + v0, xv.x);
                    v1 = fmaf(xxv.y, mc + v1, xv.y);
                }
                if (OUT == 0) {
                    *(float2*)&Yzf[off] = make_float2(v0, v1);
                } else {
                    __half2 h = __floats2half2_rn(v0, v1);
                    *(__half2*)&Yzh[off] = h;
                }
            }
        }
    }
}

// ---------------- K5: WKV6 scan, packed f32x2 + interleaved {k,k,d,d} smem ---------
// 512 thr. Thread (i = t>>3, jq = t&7) owns j-pairs {2jq+16p, 2jq+16p+1}, p=0..3.
__global__ void __launch_bounds__(512) scan_kernel(const float* __restrict__ u_in) {
    const int bh = blockIdx.x;
    const int h = bh % 12, b = bh / 12;
    const int t = threadIdx.x;
    const int jq = t & 7, i = t >> 3;          // i = 0..63
    __shared__ __align__(16) float4 kd[2][16][32];     // {k0,k1,d0,d1} per j-pair
    __shared__ __align__(16) float rbuf[2][16][68];
    __shared__ __align__(16) float vbuf[2][16][68];
    __shared__ __align__(16) float ytile[16][68];

    ull S2[4], u2[4], p2;
    #pragma unroll
    for (int p = 0; p < 4; p++) {
        S2[p] = 0ull;
        int j = 2 * jq + 16 * p;
        u2[p] = pk2(u_in[h * 64 + j], u_in[h * 64 + j + 1]);
    }

    const size_t cbase = ((size_t)b * 768 + h * 64) * 4096;
    const int csel = t >> 7, jldr = t & 63, nb = (t >> 6) & 1;
    const float* ap = (csel == 0) ? g_r : (csel == 1) ? g_k : (csel == 2) ? g_dec : g_v;
    const float* rowp = ap + cbase + (size_t)jldr * 4096;
    float* ydst = g_y + (size_t)b * 4096 * 768 + h * 64;

    float4 pre0 = *(const float4*)&rowp[nb * 4];
    float4 pre1 = *(const float4*)&rowp[(nb + 2) * 4];
    int cur = 0;
    for (int nt = 0; nt < 256; nt++) {
        {
            int s0 = nb * 4, s1 = (nb + 2) * 4;
            if (csel == 0) {
                float* c0 = &rbuf[cur][s0][jldr];
                c0[0] = pre0.x; c0[68] = pre0.y; c0[136] = pre0.z; c0[204] = pre0.w;
                float* c1 = &rbuf[cur][s1][jldr];
                c1[0] = pre1.x; c1[68] = pre1.y; c1[136] = pre1.z; c1[204] = pre1.w;
            } else if (csel == 3) {
                float* c0 = &vbuf[cur][s0][jldr];
                c0[0] = pre0.x; c0[68] = pre0.y; c0[136] = pre0.z; c0[204] = pre0.w;
                float* c1 = &vbuf[cur][s1][jldr];
                c1[0] = pre1.x; c1[68] = pre1.y; c1[136] = pre1.z; c1[204] = pre1.w;
            } else {
                // k -> lanes {0,1}, dec -> lanes {2,3} of the j-pair float4
                int off = ((csel == 1) ? 0 : 2) + (jldr & 1);
                float* c0 = (float*)&kd[cur][s0][jldr >> 1] + off;
                c0[0] = pre0.x; c0[128] = pre0.y; c0[256] = pre0.z; c0[384] = pre0.w;
                float* c1 = (float*)&kd[cur][s1][jldr >> 1] + off;
                c1[0] = pre1.x; c1[128] = pre1.y; c1[256] = pre1.z; c1[384] = pre1.w;
            }
        }
        __syncthreads();
        if (nt + 1 < 256) {
            const float* np = rowp + (nt + 1) * 16;
            pre0 = *(const float4*)&np[nb * 4];
            pre1 = *(const float4*)&np[(nb + 2) * 4];
        }
        #pragma unroll
        for (int s = 0; s < 16; s++) {
            float v = vbuf[cur][s][i];
            ull v2 = pk2(v, v);
            p2 = 0ull;
            #pragma unroll
            for (int p = 0; p < 4; p++) {
                float4 kdv = kd[cur][s][jq + 8 * p];
                ull kk = pk2(kdv.x, kdv.y);
                ull dd = pk2(kdv.z, kdv.w);
                ull rr2 = *(const ull*)&rbuf[cur][s][2 * jq + 16 * p];
                ull kv = mul2(kk, v2);
                ull tmp = fma2(u2[p], kv, S2[p]);
                p2 = fma2(rr2, tmp, p2);
                S2[p] = fma2(dd, S2[p], kv);
            }
            float plo, phi; upk2(plo, phi, p2);
            float pp = plo + phi;
            pp += __shfl_xor_sync(0xffffffffu, pp, 1);
            pp += __shfl_xor_sync(0xffffffffu, pp, 2);
            pp += __shfl_xor_sync(0xffffffffu, pp, 4);
            if (jq == 0) ytile[s][i] = pp;
        }
        __syncthreads();
        if (t < 256) {
            int tr = t >> 4, j4 = (t & 15) * 4;
            float4 o = *(float4*)&ytile[tr][j4];
            *(float4*)&ydst[(size_t)(nt * 16 + tr) * 768 + j4] = o;
        }
        cur ^= 1;
    }
}

// ---------------- K6: fused RMS + gate + transpose, fp16 channel-major out ---------
__global__ void __launch_bounds__(256) rmstgate_kernel(const float* __restrict__ lnw) {
    extern __shared__ float sy[];                 // [32][769]
    __shared__ float rmsv[32];
    const int t = threadIdx.x;
    const int tok0 = blockIdx.x * 32;
    const int b = tok0 >> 12, n0 = tok0 & 4095;
    const float* ybase = g_y + (size_t)tok0 * 768;

    #pragma unroll
    for (int it = 0; it < 24; it++) {
        int i = it * 256 + t;
        int tr = i / 192, c4 = i % 192;
        float4 v = *(const float4*)&ybase[(size_t)tr * 768 + c4 * 4];
        float* row = &sy[tr * 769];
        row[c4 * 4 + 0] = v.x; row[c4 * 4 + 1] = v.y;
        row[c4 * 4 + 2] = v.z; row[c4 * 4 + 3] = v.w;
    }
    __syncthreads();
    {
        int w = t >> 5, lane = t & 31;
        #pragma unroll
        for (int q = 0; q < 4; q++) {
            int tr = w * 4 + q;
            const float* row = &sy[tr * 769];
            float s = 0.f;
            #pragma unroll
            for (int jx = 0; jx < 24; jx++) { float v = row[lane + 32 * jx]; s += v * v; }
            #pragma unroll
            for (int off = 16; off; off >>= 1) s += __shfl_xor_sync(0xffffffffu, s, off);
            if (lane == 0) rmsv[tr] = rsqrtf(s * (1.f / 768.f) + 1e-6f);
        }
    }
    __syncthreads();
    #pragma unroll 4
    for (int it = 0; it < 96; it++) {
        int i = it * 256 + t;
        int c = i >> 5, tr = i & 31;
        float val = sy[tr * 769 + c];
        size_t go = ((size_t)(b * 768 + c)) * 4096 + n0 + tr;
        float g = __half2float(g_gateh[go]);
        g_y2h[go] = __float2half(val * rmsv[tr] * lnw[c] * g);
    }
}

// ---------------- launch ------------------------------------------------------------
extern "C" void kernel_launch(void* const* d_in, const int* in_sizes, int n_in,
                              void* d_out, int out_size) {
    const float* x        = (const float*)d_in[0];
    const float* maa_x    = (const float*)d_in[1];
    const float* maa_w    = (const float*)d_in[2];
    const float* maa_k    = (const float*)d_in[3];
    const float* maa_v    = (const float*)d_in[4];
    const float* maa_r    = (const float*)d_in[5];
    const float* maa_g    = (const float*)d_in[6];
    const float* maa_w1   = (const float*)d_in[7];
    const float* maa_w2   = (const float*)d_in[8];
    const float* tdecay   = (const float*)d_in[9];
    const float* td_w1    = (const float*)d_in[10];
    const float* td_w2    = (const float*)d_in[11];
    const float* faaaa    = (const float*)d_in[12];
    const float* key_w    = (const float*)d_in[13];
    const float* value_w  = (const float*)d_in[14];
    const float* recept_w = (const float*)d_in[15];
    const float* gate_w   = (const float*)d_in[16];
    const float* out_w    = (const float*)d_in[17];
    const float* ln_x_w   = (const float*)d_in[18];
    float* out = (float*)d_out;

    uint32_t *wh_t, *wh_w2, *wh_r, *wh_k, *wh_v, *wh_g, *wh_o, *wh_td1, *wh_td2;
    cudaGetSymbolAddress((void**)&wh_t,   g_wh_t);
    cudaGetSymbolAddress((void**)&wh_w2,  g_wh_w2);
    cudaGetSymbolAddress((void**)&wh_r,   g_wh_r);
    cudaGetSymbolAddress((void**)&wh_k,   g_wh_k);
    cudaGetSymbolAddress((void**)&wh_v,   g_wh_v);
    cudaGetSymbolAddress((void**)&wh_g,   g_wh_g);
    cudaGetSymbolAddress((void**)&wh_o,   g_wh_o);
    cudaGetSymbolAddress((void**)&wh_td1, g_wh_td1);
    cudaGetSymbolAddress((void**)&wh_td2, g_wh_td2);
    float *p_r, *p_k, *p_v, *p_dec;
    __half *p_xxxh, *p_th, *p_x5h, *p_gateh, *p_hh, *p_y2h;
    cudaGetSymbolAddress((void**)&p_xxxh, g_xxxh);
    cudaGetSymbolAddress((void**)&p_th,   g_th);
    cudaGetSymbolAddress((void**)&p_x5h,  g_x5h);
    cudaGetSymbolAddress((void**)&p_gateh,g_gateh);
    cudaGetSymbolAddress((void**)&p_hh,   g_hh);
    cudaGetSymbolAddress((void**)&p_y2h,  g_y2h);
    cudaGetSymbolAddress((void**)&p_r,    g_r);
    cudaGetSymbolAddress((void**)&p_k,    g_k);
    cudaGetSymbolAddress((void**)&p_v,    g_v);
    cudaGetSymbolAddress((void**)&p_dec,  g_dec);

    // one merged weight-prep launch (1081344 elems / 256 = 4224 blocks)
    prep_all<<<4224, 256>>>(maa_w1, maa_w2, recept_w, key_w, value_w,
                            gate_w, out_w, td_w1, td_w2);

    shift_kernel<<<(BCN + 255) / 256, 256>>>(x, maa_x);

    #define NUL5 nullptr, nullptr, nullptr, nullptr, nullptr
    long long sC    = (long long)Cc * Nn;
    long long s384  = (long long)384 * Nn;
    long long s128  = (long long)128 * Nn;

    gemm_h<1,1><<<dim3(32, 3, 8), 256>>>(wh_t, p_xxxh, p_th, 384, 768, 1,
                                         sC, s384, nullptr, nullptr, NUL5);

    gemm_h<4,1><<<dim3(32, 6, 40), 256>>>(wh_w2, p_th, p_x5h, 768, 64, 5,
                                          0, sC, nullptr, x,
                                          maa_w, maa_k, maa_v, maa_r, maa_g);

    gemm_h<0,0><<<dim3(32, 3, 16), 256>>>(wh_r, p_x5h + (size_t)3*BCN, p_r, 384, 384, 2,
                                          s384, s384, nullptr, nullptr, NUL5);
    gemm_h<0,0><<<dim3(32, 3, 16), 256>>>(wh_k, p_x5h + (size_t)1*BCN, p_k, 384, 384, 2,
                                          s384, s384, nullptr, nullptr, NUL5);
    gemm_h<0,0><<<dim3(32, 3, 16), 256>>>(wh_v, p_x5h + (size_t)2*BCN, p_v, 384, 384, 2,
                                          s384, s384, nullptr, nullptr, NUL5);
    gemm_h<2,1><<<dim3(32, 3, 16), 256>>>(wh_g, p_x5h + (size_t)4*BCN, p_gateh, 384, 384, 2,
                                          s384, s384, nullptr, nullptr, NUL5);

    gemm_h<1,1><<<dim3(32, 1, 8), 256>>>(wh_td1, p_x5h, p_hh, 128, 768, 1,
                                         sC, s128, nullptr, nullptr, NUL5);
    gemm_h<3,0><<<dim3(32, 6, 8), 256>>>(wh_td2, p_hh, p_dec, 768, 64, 1,
                                         s128, sC, tdecay, nullptr, NUL5);

    scan_kernel<<<96, 512>>>(faaaa);

    cudaFuncSetAttribute(rmstgate_kernel, cudaFuncAttributeMaxDynamicSharedMemorySize,
                         32 * 769 * 4);
    rmstgate_kernel<<<TOK / 32, 256, 32 * 769 * 4>>>(ln_x_w);

    gemm_h<0,0><<<dim3(32, 3, 16), 256>>>(wh_o, p_y2h, out, 384, 384, 2,
                                          s384, s384, nullptr, nullptr, NUL5);
}

// round 15
// speedup vs baseline: 1.0453x; 1.0453x over previous
#include <cuda_runtime.h>
#include <cuda_fp16.h>
#include <cstdint>
#include <cstddef>

#define Bb 8
#define Cc 768
#define Nn 4096
#define TOK (Bb*Nn)
#define BCN (Bb*Cc*Nn)   // 25165824

typedef unsigned long long ull;

// ---------------- scratch (static device globals) ---------------------------------
__device__ __align__(16) float2 g_xxp [BCN];              // {x, xx} interleaved (b,c,n)
__device__ __align__(16) __half g_xxxh[BCN];              // fp16 (mma operand only)
__device__ __align__(16) __half g_th  [Bb*384*Nn];        // t, fp16
__device__ __align__(16) __half g_x5h [5u*(size_t)BCN];   // s: 0=xw 1=xk 2=xv 3=xr 4=xg
__device__ __align__(16) __half g_gateh[BCN];
__device__ __align__(16) __half g_hh  [(size_t)Bb*128*Nn];// decay hidden fp16 (padded)
__device__ __align__(16) float  g_r   [BCN];              // conv outputs fp32 (b,c,n)
__device__ __align__(16) float  g_k   [BCN];
__device__ __align__(16) float  g_v   [BCN];
__device__ __align__(16) float  g_dec [BCN];
__device__ __align__(16) float  g_y   [BCN];              // scan out (b,n,c)
__device__ __align__(16) __half g_y2h [BCN];              // normalized+gated (b,c,n)
// fp16 fragment-packed weights: [z][kt][mfr][lane][4] uint32 (half2)
__device__ __align__(16) uint32_t g_wh_t  [48*24*128];
__device__ __align__(16) uint32_t g_wh_w2 [5*4*48*128];
__device__ __align__(16) uint32_t g_wh_r  [2*24*24*128];
__device__ __align__(16) uint32_t g_wh_k  [2*24*24*128];
__device__ __align__(16) uint32_t g_wh_v  [2*24*24*128];
__device__ __align__(16) uint32_t g_wh_g  [2*24*24*128];
__device__ __align__(16) uint32_t g_wh_o  [2*24*24*128];
__device__ __align__(16) uint32_t g_wh_td1[48*8*128];
__device__ __align__(16) uint32_t g_wh_td2[4*48*128];

// ---------------- asm helpers ------------------------------------------------------
__device__ __forceinline__ uint32_t s2u(const void* p) {
    uint32_t a;
    asm("{ .reg .u64 t; cvta.to.shared.u64 t, %1; cvt.u32.u64 %0, t; }" : "=r"(a) : "l"(p));
    return a;
}
__device__ __forceinline__ void mma16(float* d, const uint4& a, uint32_t b0, uint32_t b1) {
    asm volatile("mma.sync.aligned.m16n8k16.row.col.f32.f16.f16.f32 "
        "{%0,%1,%2,%3}, {%4,%5,%6,%7}, {%8,%9}, {%0,%1,%2,%3};"
        : "+f"(d[0]), "+f"(d[1]), "+f"(d[2]), "+f"(d[3])
        : "r"(a.x), "r"(a.y), "r"(a.z), "r"(a.w), "r"(b0), "r"(b1));
}
__device__ __forceinline__ void ldmB(uint32_t& b0, uint32_t& b1, uint32_t addr) {
    asm volatile("ldmatrix.sync.aligned.m8n8.x2.trans.shared.b16 {%0,%1}, [%2];"
        : "=r"(b0), "=r"(b1) : "r"(addr));
}
// packed f32x2 ops (sm_103a)
__device__ __forceinline__ ull pk2(float lo, float hi) {
    ull d; asm("mov.b64 %0, {%1, %2};" : "=l"(d) : "f"(lo), "f"(hi)); return d;
}
__device__ __forceinline__ void upk2(float& lo, float& hi, ull v) {
    asm("mov.b64 {%0, %1}, %2;" : "=f"(lo), "=f"(hi) : "l"(v));
}
__device__ __forceinline__ ull mul2(ull a, ull b) {
    ull d; asm("mul.rn.f32x2 %0, %1, %2;" : "=l"(d) : "l"(a), "l"(b)); return d;
}
__device__ __forceinline__ ull fma2(ull a, ull b, ull c) {
    ull d; asm("fma.rn.f32x2 %0, %1, %2, %3;" : "=l"(d) : "l"(a), "l"(b), "l"(c)); return d;
}

// ---------------- K0: merged weight prep (one launch, table dispatch) --------------
__device__ __forceinline__ void pack_one(const float* __restrict__ src,
                                         uint32_t* __restrict__ dst,
                                         int M, int Mp, int K, int trans, size_t idx) {
    int KT = K >> 4, MFR = Mp >> 4;
    size_t per_z = (size_t)KT * MFR * 128;
    int z = (int)(idx / per_z);
    size_t rem = idx - (size_t)z * per_z;
    int kt  = (int)(rem / (MFR * 128));
    int r2  = (int)(rem % (MFR * 128));
    int mfr = r2 >> 7;
    int li  = r2 & 127;
    int lane = li >> 2, r = li & 3;
    int m = mfr * 16 + (lane >> 2) + ((r & 1) << 3);
    int k = kt * 16 + (lane & 3) * 2 + ((r >> 1) << 3);
    float f0 = 0.f, f1 = 0.f;
    if (m < M) {
        const float* sz = src + (size_t)z * M * K;
        if (trans) { f0 = sz[(size_t)k * M + m]; f1 = sz[(size_t)(k + 1) * M + m]; }
        else       { f0 = sz[(size_t)m * K + k]; f1 = sz[(size_t)m * K + k + 1]; }
    }
    __half2 h = __floats2half2_rn(f0, f1);
    dst[idx] = *(uint32_t*)&h;
}

__global__ void prep_all(const float* s_t, const float* s_w2, const float* s_r,
                         const float* s_k, const float* s_v, const float* s_g,
                         const float* s_o, const float* s_td1, const float* s_td2) {
    size_t idx = (size_t)blockIdx.x * 256 + threadIdx.x;
    if (idx < 147456)        pack_one(s_t,   g_wh_t,   320, 384, 768, 0, idx);
    else if (idx < 270336)   pack_one(s_w2,  g_wh_w2,  768, 768,  64, 1, idx - 147456);
    else if (idx < 417792)   pack_one(s_r,   g_wh_r,   384, 384, 384, 0, idx - 270336);
    else if (idx < 565248)   pack_one(s_k,   g_wh_k,   384, 384, 384, 0, idx - 417792);
    else if (idx < 712704)   pack_one(s_v,   g_wh_v,   384, 384, 384, 0, idx - 565248);
    else if (idx < 860160)   pack_one(s_g,   g_wh_g,   384, 384, 384, 0, idx - 712704);
    else if (idx < 1007616)  pack_one(s_o,   g_wh_o,   384, 384, 384, 0, idx - 860160);
    else if (idx < 1056768)  pack_one(s_td1, g_wh_td1,  64, 128, 768, 0, idx - 1007616);
    else if (idx < 1081344)  pack_one(s_td2, g_wh_td2, 768, 768,  64, 0, idx - 1056768);
}

// ---------------- K1: q_shift + {x,xx}(float2) + xxx(fp16) -------------------------
__global__ void shift_kernel(const float* __restrict__ x, const float* __restrict__ maa_x) {
    size_t idx = (size_t)blockIdx.x * 256 + threadIdx.x;
    if (idx >= (size_t)BCN) return;
    int n = (int)(idx & (Nn - 1));
    int c = (int)((idx >> 12) % Cc);
    int w = n & 63, hh = n >> 6;
    float xv = x[idx], s;
    int mode = c / 192;
    if (mode == 0)      s = (w  > 0 ) ? x[idx - 1 ] : 0.f;
    else if (mode == 1) s = (w  < 63) ? x[idx + 1 ] : 0.f;
    else if (mode == 2) s = (hh > 0 ) ? x[idx - 64] : 0.f;
    else                s = (hh < 63) ? x[idx + 64] : 0.f;
    float d = s - xv;
    g_xxp[idx]  = make_float2(xv, d);
    g_xxxh[idx] = __float2half(fmaf(d, maa_x[c], xv));
}

// ---------------- fp16 tensor-core GEMM (R12-proven two-barrier mainloop) ----------
// ACT: 0 none, 1 tanh, 2 silu, 3 decay exp(-exp(extra[m]+v)), 4 mix fuse (z=b*5+s)
// OUT: 0 fp32, 1 fp16
template<int ACT, int OUT>
__global__ void __launch_bounds__(256) gemm_h(
    const uint32_t* __restrict__ Wp, const __half* __restrict__ X,
    void* __restrict__ Yv, int Mp, int K, int wmod,
    long long sXz, long long sYz,
    const float* __restrict__ extra,
    const float* __restrict__ q0, const float* __restrict__ q1,
    const float* __restrict__ q2, const float* __restrict__ q3,
    const float* __restrict__ q4)
{
    const int z   = blockIdx.z;
    const int m0g = blockIdx.y * 128;
    const int n0g = blockIdx.x * 128;
    const int KT = K >> 4, MFR = Mp >> 4;

    const uint32_t* Wz;
    const __half* Xz;
    float* Yzf = nullptr; __half* Yzh = nullptr;
    const float* maa = nullptr; const float2* xpb = nullptr;
    if (ACT == 4) {
        int s = z % 5, b = z / 5;
        Wz = Wp + (size_t)s * KT * MFR * 128;
        Xz = X + (size_t)b * 384 * Nn + (size_t)s * 64 * Nn;
        Yzh = (__half*)Yv + (size_t)(s * 8 + b) * sYz;
        maa = (s==0)?q0:(s==1)?q1:(s==2)?q2:(s==3)?q3:q4;
        xpb = g_xxp + (size_t)b * Cc * Nn;
    } else {
        Wz = Wp + (size_t)(z % wmod) * KT * MFR * 128;
        Xz = X + (size_t)z * sXz;
        if (OUT == 0) Yzf = (float*)Yv + (size_t)z * sYz;
        else          Yzh = (__half*)Yv + (size_t)z * sYz;
    }

    __shared__ __align__(16) __half Bs[2][16][136];

    const int t = threadIdx.x;
    const int lane = t & 31, wid = t >> 5;
    const int wm = wid >> 2, wn = wid & 3;
    const int kRow = t >> 4, c8 = (t & 15) * 8;

    float acc[4][4][4];
    #pragma unroll
    for (int i = 0; i < 4; i++)
        #pragma unroll
        for (int jx = 0; jx < 4; jx++)
            #pragma unroll
            for (int q = 0; q < 4; q++) acc[i][jx][q] = 0.f;

    uint4 aR[2][4];
    uint4 bRh;

    #pragma unroll
    for (int mf = 0; mf < 4; mf++) {
        int mfr = (m0g >> 4) + wm * 4 + mf;
        aR[0][mf] = *(const uint4*)&Wz[(((size_t)0 * MFR + mfr) * 32 + lane) * 4];
    }
    bRh = *(const uint4*)&Xz[(size_t)kRow * Nn + n0g + c8];

    for (int kt = 0; kt < KT; kt++) {
        int buf = kt & 1;
        *(uint4*)&Bs[buf][kRow][c8] = bRh;
        __syncthreads();
        if (kt + 1 < KT) {
            #pragma unroll
            for (int mf = 0; mf < 4; mf++) {
                int mfr = (m0g >> 4) + wm * 4 + mf;
                aR[buf ^ 1][mf] =
                    *(const uint4*)&Wz[(((size_t)(kt + 1) * MFR + mfr) * 32 + lane) * 4];
            }
            bRh = *(const uint4*)&Xz[(size_t)((kt + 1) * 16 + kRow) * Nn + n0g + c8];
        }
        uint32_t base = s2u(&Bs[buf][lane & 15][wn * 32]);
        uint32_t bf[4][2];
        #pragma unroll
        for (int nf = 0; nf < 4; nf++) ldmB(bf[nf][0], bf[nf][1], base + nf * 16);
        #pragma unroll
        for (int mf = 0; mf < 4; mf++)
            #pragma unroll
            for (int nf = 0; nf < 4; nf++)
                mma16(acc[mf][nf], aR[buf][mf], bf[nf][0], bf[nf][1]);
        __syncthreads();
    }

    #pragma unroll
    for (int mf = 0; mf < 4; mf++) {
        int rr0 = m0g + wm * 64 + mf * 16 + (lane >> 2);
        #pragma unroll
        for (int hf = 0; hf < 2; hf++) {
            int rr = rr0 + hf * 8;
            float e  = (ACT == 3) ? extra[rr] : 0.f;
            float mc = (ACT == 4) ? maa[rr]   : 0.f;
            #pragma unroll
            for (int nf = 0; nf < 4; nf++) {
                int nc = n0g + wn * 32 + nf * 8 + (lane & 3) * 2;
                float v0 = acc[mf][nf][hf * 2 + 0];
                float v1 = acc[mf][nf][hf * 2 + 1];
                size_t off = (size_t)rr * Nn + nc;
                if (ACT == 1) { v0 = tanhf(v0); v1 = tanhf(v1); }
                else if (ACT == 2) { v0 = v0 / (1.f + expf(-v0)); v1 = v1 / (1.f + expf(-v1)); }
                else if (ACT == 3) { v0 = expf(-expf(e + v0)); v1 = expf(-expf(e + v1)); }
                else if (ACT == 4) {
                    float4 xp = *(const float4*)&xpb[off];   // {x0, xx0, x1, xx1}
                    v0 = fmaf(xp.y, mc + v0, xp.x);
                    v1 = fmaf(xp.w, mc + v1, xp.z);
                }
                if (OUT == 0) {
                    *(float2*)&Yzf[off] = make_float2(v0, v1);
                } else {
                    __half2 h = __floats2half2_rn(v0, v1);
                    *(__half2*)&Yzh[off] = h;
                }
            }
        }
    }
}

// ---------------- K5: WKV6 scan, packed f32x2 (R12-proven) -------------------------
__global__ void __launch_bounds__(512) scan_kernel(const float* __restrict__ u_in) {
    const int bh = blockIdx.x;
    const int h = bh % 12, b = bh / 12;
    const int t = threadIdx.x;
    const int jq = t & 7, i = t >> 3;          // i = 0..63
    __shared__ __align__(16) float sm[4][2][16][68];   // comp r,k,d,v
    __shared__ __align__(16) float ytile[16][68];

    ull S2[4], u2[4], p2;
    #pragma unroll
    for (int p = 0; p < 4; p++) {
        S2[p] = 0ull;
        int j = 2 * jq + 16 * p;
        u2[p] = pk2(u_in[h * 64 + j], u_in[h * 64 + j + 1]);
    }

    const size_t cbase = ((size_t)b * 768 + h * 64) * 4096;
    const int csel = t >> 7, jldr = t & 63, nb = (t >> 6) & 1;
    const float* ap = (csel == 0) ? g_r : (csel == 1) ? g_k : (csel == 2) ? g_dec : g_v;
    const float* rowp = ap + cbase + (size_t)jldr * 4096;
    float* ydst = g_y + (size_t)b * 4096 * 768 + h * 64;

    float4 pre0 = *(const float4*)&rowp[nb * 4];
    float4 pre1 = *(const float4*)&rowp[(nb + 2) * 4];
    int cur = 0;
    for (int nt = 0; nt < 256; nt++) {
        {
            float* c0 = &sm[csel][cur][nb * 4][jldr];
            c0[0] = pre0.x; c0[68] = pre0.y; c0[136] = pre0.z; c0[204] = pre0.w;
            float* c1 = &sm[csel][cur][(nb + 2) * 4][jldr];
            c1[0] = pre1.x; c1[68] = pre1.y; c1[136] = pre1.z; c1[204] = pre1.w;
        }
        __syncthreads();
        if (nt + 1 < 256) {
            const float* np = rowp + (nt + 1) * 16;
            pre0 = *(const float4*)&np[nb * 4];
            pre1 = *(const float4*)&np[(nb + 2) * 4];
        }
        #pragma unroll
        for (int s = 0; s < 16; s++) {
            float v = sm[3][cur][s][i];
            ull v2 = pk2(v, v);
            p2 = 0ull;
            #pragma unroll
            for (int p = 0; p < 4; p++) {
                int j = 2 * jq + 16 * p;
                ull kk = *(const ull*)&sm[1][cur][s][j];
                ull dd = *(const ull*)&sm[2][cur][s][j];
                ull rr = *(const ull*)&sm[0][cur][s][j];
                ull kv = mul2(kk, v2);
                ull tmp = fma2(u2[p], kv, S2[p]);
                p2 = fma2(rr, tmp, p2);
                S2[p] = fma2(dd, S2[p], kv);
            }
            float plo, phi; upk2(plo, phi, p2);
            float pp = plo + phi;
            pp += __shfl_xor_sync(0xffffffffu, pp, 1);
            pp += __shfl_xor_sync(0xffffffffu, pp, 2);
            pp += __shfl_xor_sync(0xffffffffu, pp, 4);
            if (jq == 0) ytile[s][i] = pp;
        }
        __syncthreads();
        if (t < 256) {
            int tr = t >> 4, j4 = (t & 15) * 4;
            float4 o = *(float4*)&ytile[tr][j4];
            *(float4*)&ydst[(size_t)(nt * 16 + tr) * 768 + j4] = o;
        }
        cur ^= 1;
    }
}

// ---------------- K6: fused RMS + gate + transpose, fp16 channel-major out ---------
__global__ void __launch_bounds__(256) rmstgate_kernel(const float* __restrict__ lnw) {
    extern __shared__ float sy[];                 // [32][769]
    __shared__ float rmsv[32];
    const int t = threadIdx.x;
    const int tok0 = blockIdx.x * 32;
    const int b = tok0 >> 12, n0 = tok0 & 4095;
    const float* ybase = g_y + (size_t)tok0 * 768;

    #pragma unroll
    for (int it = 0; it < 24; it++) {
        int i = it * 256 + t;
        int tr = i / 192, c4 = i % 192;
        float4 v = *(const float4*)&ybase[(size_t)tr * 768 + c4 * 4];
        float* row = &sy[tr * 769];
        row[c4 * 4 + 0] = v.x; row[c4 * 4 + 1] = v.y;
        row[c4 * 4 + 2] = v.z; row[c4 * 4 + 3] = v.w;
    }
    __syncthreads();
    {
        int w = t >> 5, lane = t & 31;
        #pragma unroll
        for (int q = 0; q < 4; q++) {
            int tr = w * 4 + q;
            const float* row = &sy[tr * 769];
            float s = 0.f;
            #pragma unroll
            for (int jx = 0; jx < 24; jx++) { float v = row[lane + 32 * jx]; s += v * v; }
            #pragma unroll
            for (int off = 16; off; off >>= 1) s += __shfl_xor_sync(0xffffffffu, s, off);
            if (lane == 0) rmsv[tr] = rsqrtf(s * (1.f / 768.f) + 1e-6f);
        }
    }
    __syncthreads();
    #pragma unroll 4
    for (int it = 0; it < 96; it++) {
        int i = it * 256 + t;
        int c = i >> 5, tr = i & 31;
        float val = sy[tr * 769 + c];
        size_t go = ((size_t)(b * 768 + c)) * 4096 + n0 + tr;
        float g = __half2float(g_gateh[go]);
        g_y2h[go] = __float2half(val * rmsv[tr] * lnw[c] * g);
    }
}

// ---------------- launch ------------------------------------------------------------
extern "C" void kernel_launch(void* const* d_in, const int* in_sizes, int n_in,
                              void* d_out, int out_size) {
    const float* x        = (const float*)d_in[0];
    const float* maa_x    = (const float*)d_in[1];
    const float* maa_w    = (const float*)d_in[2];
    const float* maa_k    = (const float*)d_in[3];
    const float* maa_v    = (const float*)d_in[4];
    const float* maa_r    = (const float*)d_in[5];
    const float* maa_g    = (const float*)d_in[6];
    const float* maa_w1   = (const float*)d_in[7];
    const float* maa_w2   = (const float*)d_in[8];
    const float* tdecay   = (const float*)d_in[9];
    const float* td_w1    = (const float*)d_in[10];
    const float* td_w2    = (const float*)d_in[11];
    const float* faaaa    = (const float*)d_in[12];
    const float* key_w    = (const float*)d_in[13];
    const float* value_w  = (const float*)d_in[14];
    const float* recept_w = (const float*)d_in[15];
    const float* gate_w   = (const float*)d_in[16];
    const float* out_w    = (const float*)d_in[17];
    const float* ln_x_w   = (const float*)d_in[18];
    float* out = (float*)d_out;

    uint32_t *wh_t, *wh_w2, *wh_r, *wh_k, *wh_v, *wh_g, *wh_o, *wh_td1, *wh_td2;
    cudaGetSymbolAddress((void**)&wh_t,   g_wh_t);
    cudaGetSymbolAddress((void**)&wh_w2,  g_wh_w2);
    cudaGetSymbolAddress((void**)&wh_r,   g_wh_r);
    cudaGetSymbolAddress((void**)&wh_k,   g_wh_k);
    cudaGetSymbolAddress((void**)&wh_v,   g_wh_v);
    cudaGetSymbolAddress((void**)&wh_g,   g_wh_g);
    cudaGetSymbolAddress((void**)&wh_o,   g_wh_o);
    cudaGetSymbolAddress((void**)&wh_td1, g_wh_td1);
    cudaGetSymbolAddress((void**)&wh_td2, g_wh_td2);
    float *p_r, *p_k, *p_v, *p_dec;
    __half *p_xxxh, *p_th, *p_x5h, *p_gateh, *p_hh, *p_y2h;
    cudaGetSymbolAddress((void**)&p_xxxh, g_xxxh);
    cudaGetSymbolAddress((void**)&p_th,   g_th);
    cudaGetSymbolAddress((void**)&p_x5h,  g_x5h);
    cudaGetSymbolAddress((void**)&p_gateh,g_gateh);
    cudaGetSymbolAddress((void**)&p_hh,   g_hh);
    cudaGetSymbolAddress((void**)&p_y2h,  g_y2h);
    cudaGetSymbolAddress((void**)&p_r,    g_r);
    cudaGetSymbolAddress((void**)&p_k,    g_k);
    cudaGetSymbolAddress((void**)&p_v,    g_v);
    cudaGetSymbolAddress((void**)&p_dec,  g_dec);

    prep_all<<<4224, 256>>>(maa_w1, maa_w2, recept_w, key_w, value_w,
                            gate_w, out_w, td_w1, td_w2);

    shift_kernel<<<(BCN + 255) / 256, 256>>>(x, maa_x);

    #define NUL5 nullptr, nullptr, nullptr, nullptr, nullptr
    long long sC    = (long long)Cc * Nn;
    long long s384  = (long long)384 * Nn;
    long long s128  = (long long)128 * Nn;

    gemm_h<1,1><<<dim3(32, 3, 8), 256>>>(wh_t, p_xxxh, p_th, 384, 768, 1,
                                         sC, s384, nullptr, NUL5);

    gemm_h<4,1><<<dim3(32, 6, 40), 256>>>(wh_w2, p_th, p_x5h, 768, 64, 5,
                                          0, sC, nullptr,
                                          maa_w, maa_k, maa_v, maa_r, maa_g);

    gemm_h<0,0><<<dim3(32, 3, 16), 256>>>(wh_r, p_x5h + (size_t)3*BCN, p_r, 384, 384, 2,
                                          s384, s384, nullptr, NUL5);
    gemm_h<0,0><<<dim3(32, 3, 16), 256>>>(wh_k, p_x5h + (size_t)1*BCN, p_k, 384, 384, 2,
                                          s384, s384, nullptr, NUL5);
    gemm_h<0,0><<<dim3(32, 3, 16), 256>>>(wh_v, p_x5h + (size_t)2*BCN, p_v, 384, 384, 2,
                                          s384, s384, nullptr, NUL5);
    gemm_h<2,1><<<dim3(32, 3, 16), 256>>>(wh_g, p_x5h + (size_t)4*BCN, p_gateh, 384, 384, 2,
                                          s384, s384, nullptr, NUL5);

    gemm_h<1,1><<<dim3(32, 1, 8), 256>>>(wh_td1, p_x5h, p_hh, 128, 768, 1,
                                         sC, s128, nullptr, NUL5);
    gemm_h<3,0><<<dim3(32, 6, 8), 256>>>(wh_td2, p_hh, p_dec, 768, 64, 1,
                                         s128, sC, tdecay, NUL5);

    scan_kernel<<<96, 512>>>(faaaa);

    cudaFuncSetAttribute(rmstgate_kernel, cudaFuncAttributeMaxDynamicSharedMemorySize,
                         32 * 769 * 4);
    rmstgate_kernel<<<TOK / 32, 256, 32 * 769 * 4>>>(ln_x_w);

    gemm_h<0,0><<<dim3(32, 3, 16), 256>>>(wh_o, p_y2h, out, 384, 384, 2,
                                          s384, s384, nullptr, NUL5);
}

// round 17
// speedup vs baseline: 1.1149x; 1.0666x over previous
#include <cuda_runtime.h>
#include <cuda_fp16.h>
#include <cstdint>
#include <cstddef>

#define Bb 8
#define Cc 768
#define Nn 4096
#define TOK (Bb*Nn)
#define BCN (Bb*Cc*Nn)   // 25165824

typedef unsigned long long ull;

// ---------------- scratch (static device globals) ---------------------------------
__device__ __align__(16) __half2 g_xph[BCN];              // {x, xx} packed half2 (b,c,n)
__device__ __align__(16) __half g_xxxh[BCN];              // fp16 (mma operand only)
__device__ __align__(16) __half g_th  [Bb*384*Nn];        // t, fp16
__device__ __align__(16) __half g_x5h [5u*(size_t)BCN];   // s: 0=xw 1=xk 2=xv 3=xr 4=xg
__device__ __align__(16) __half g_gateh[BCN];
__device__ __align__(16) __half g_hh  [(size_t)Bb*128*Nn];// decay hidden fp16 (padded)
__device__ __align__(16) float  g_r   [BCN];              // conv outputs fp32 (b,c,n)
__device__ __align__(16) float  g_k   [BCN];
__device__ __align__(16) float  g_v   [BCN];
__device__ __align__(16) float  g_dec [BCN];
__device__ __align__(16) float  g_y   [BCN];              // scan out (b,n,c)
__device__ __align__(16) __half g_y2h [BCN];              // normalized+gated (b,c,n)
// fp16 weights in ldmatrix-ready layout: [z][kt][mfr][128 u32]
// u32 q in [0,128): tile=q>>5, row=(q>>2)&7, col2=q&3
//   m = mfr*16 + row + (tile&1)*8 ; k = kt*16 + (tile>>1)*8 + col2*2
__device__ __align__(16) uint32_t g_wh_t  [48*24*128];
__device__ __align__(16) uint32_t g_wh_w2 [5*4*48*128];
__device__ __align__(16) uint32_t g_wh_r  [2*24*24*128];
__device__ __align__(16) uint32_t g_wh_k  [2*24*24*128];
__device__ __align__(16) uint32_t g_wh_v  [2*24*24*128];
__device__ __align__(16) uint32_t g_wh_g  [2*24*24*128];
__device__ __align__(16) uint32_t g_wh_o  [2*24*24*128];
__device__ __align__(16) uint32_t g_wh_td1[48*8*128];
__device__ __align__(16) uint32_t g_wh_td2[4*48*128];

// ---------------- asm helpers ------------------------------------------------------
__device__ __forceinline__ uint32_t s2u(const void* p) {
    uint32_t a;
    asm("{ .reg .u64 t; cvta.to.shared.u64 t, %1; cvt.u32.u64 %0, t; }" : "=r"(a) : "l"(p));
    return a;
}
__device__ __forceinline__ void mma16(float* d, const uint4& a, uint32_t b0, uint32_t b1) {
    asm volatile("mma.sync.aligned.m16n8k16.row.col.f32.f16.f16.f32 "
        "{%0,%1,%2,%3}, {%4,%5,%6,%7}, {%8,%9}, {%0,%1,%2,%3};"
        : "+f"(d[0]), "+f"(d[1]), "+f"(d[2]), "+f"(d[3])
        : "r"(a.x), "r"(a.y), "r"(a.z), "r"(a.w), "r"(b0), "r"(b1));
}
__device__ __forceinline__ void ldmB(uint32_t& b0, uint32_t& b1, uint32_t addr) {
    asm volatile("ldmatrix.sync.aligned.m8n8.x2.trans.shared.b16 {%0,%1}, [%2];"
        : "=r"(b0), "=r"(b1) : "r"(addr));
}
__device__ __forceinline__ void ldmA(uint4& a, uint32_t addr) {
    asm volatile("ldmatrix.sync.aligned.m8n8.x4.shared.b16 {%0,%1,%2,%3}, [%4];"
        : "=r"(a.x), "=r"(a.y), "=r"(a.z), "=r"(a.w) : "r"(addr));
}
// packed f32x2 ops (sm_103a)
__device__ __forceinline__ ull pk2(float lo, float hi) {
    ull d; asm("mov.b64 %0, {%1, %2};" : "=l"(d) : "f"(lo), "f"(hi)); return d;
}
__device__ __forceinline__ void upk2(float& lo, float& hi, ull v) {
    asm("mov.b64 {%0, %1}, %2;" : "=f"(lo), "=f"(hi) : "l"(v));
}
__device__ __forceinline__ ull mul2(ull a, ull b) {
    ull d; asm("mul.rn.f32x2 %0, %1, %2;" : "=l"(d) : "l"(a), "l"(b)); return d;
}
__device__ __forceinline__ ull fma2(ull a, ull b, ull c) {
    ull d; asm("fma.rn.f32x2 %0, %1, %2, %3;" : "=l"(d) : "l"(a), "l"(b), "l"(c)); return d;
}

// ---------------- K0: merged weight prep (ldmatrix-tile layout) --------------------
__device__ __forceinline__ void pack_one(const float* __restrict__ src,
                                         uint32_t* __restrict__ dst,
                                         int M, int Mp, int K, int trans, size_t idx) {
    int KT = K >> 4, MFR = Mp >> 4;
    size_t per_z = (size_t)KT * MFR * 128;
    int z = (int)(idx / per_z);
    size_t rem = idx - (size_t)z * per_z;
    int kt  = (int)(rem / (MFR * 128));
    int r2  = (int)(rem % (MFR * 128));
    int mfr = r2 >> 7;
    int q   = r2 & 127;
    int tile = q >> 5, row = (q >> 2) & 7, col2 = q & 3;
    int m = mfr * 16 + row + ((tile & 1) << 3);
    int k = kt * 16 + ((tile >> 1) << 3) + col2 * 2;
    float f0 = 0.f, f1 = 0.f;
    if (m < M) {
        const float* sz = src + (size_t)z * M * K;
        if (trans) { f0 = sz[(size_t)k * M + m]; f1 = sz[(size_t)(k + 1) * M + m]; }
        else       { f0 = sz[(size_t)m * K + k]; f1 = sz[(size_t)m * K + k + 1]; }
    }
    __half2 h = __floats2half2_rn(f0, f1);
    dst[idx] = *(uint32_t*)&h;
}

__global__ void prep_all(const float* s_t, const float* s_w2, const float* s_r,
                         const float* s_k, const float* s_v, const float* s_g,
                         const float* s_o, const float* s_td1, const float* s_td2) {
    size_t idx = (size_t)blockIdx.x * 256 + threadIdx.x;
    if (idx < 147456)        pack_one(s_t,   g_wh_t,   320, 384, 768, 0, idx);
    else if (idx < 270336)   pack_one(s_w2,  g_wh_w2,  768, 768,  64, 1, idx - 147456);
    else if (idx < 417792)   pack_one(s_r,   g_wh_r,   384, 384, 384, 0, idx - 270336);
    else if (idx < 565248)   pack_one(s_k,   g_wh_k,   384, 384, 384, 0, idx - 417792);
    else if (idx < 712704)   pack_one(s_v,   g_wh_v,   384, 384, 384, 0, idx - 565248);
    else if (idx < 860160)   pack_one(s_g,   g_wh_g,   384, 384, 384, 0, idx - 712704);
    else if (idx < 1007616)  pack_one(s_o,   g_wh_o,   384, 384, 384, 0, idx - 860160);
    else if (idx < 1056768)  pack_one(s_td1, g_wh_td1,  64, 128, 768, 0, idx - 1007616);
    else if (idx < 1081344)  pack_one(s_td2, g_wh_td2, 768, 768,  64, 0, idx - 1056768);
}

// ---------------- K1: q_shift + {x,xx}(half2) + xxx(fp16) --------------------------
__global__ void shift_kernel(const float* __restrict__ x, const float* __restrict__ maa_x) {
    size_t idx = (size_t)blockIdx.x * 256 + threadIdx.x;
    if (idx >= (size_t)BCN) return;
    int n = (int)(idx & (Nn - 1));
    int c = (int)((idx >> 12) % Cc);
    int w = n & 63, hh = n >> 6;
    float xv = x[idx], s;
    int mode = c / 192;
    if (mode == 0)      s = (w  > 0 ) ? x[idx - 1 ] : 0.f;
    else if (mode == 1) s = (w  < 63) ? x[idx + 1 ] : 0.f;
    else if (mode == 2) s = (hh > 0 ) ? x[idx - 64] : 0.f;
    else                s = (hh < 63) ? x[idx + 64] : 0.f;
    float d = s - xv;
    g_xph[idx]  = __floats2half2_rn(xv, d);          // low=x, high=xx
    g_xxxh[idx] = __float2half(fmaf(d, maa_x[c], xv));
}

// ---------------- fp16 tensor-core GEMM: smem A (ldmatrix) + smem B ----------------
// ACT: 0 none, 1 tanh, 2 silu, 3 decay exp(-exp(extra[m]+v)), 4 mix fuse (z=b*5+s)
// OUT: 0 fp32, 1 fp16
template<int ACT, int OUT>
__global__ void __launch_bounds__(256) gemm_h(
    const uint32_t* __restrict__ Wp, const __half* __restrict__ X,
    void* __restrict__ Yv, int Mp, int K, int wmod,
    long long sXz, long long sYz,
    const float* __restrict__ extra,
    const float* __restrict__ q0, const float* __restrict__ q1,
    const float* __restrict__ q2, const float* __restrict__ q3,
    const float* __restrict__ q4)
{
    const int z   = blockIdx.z;
    const int m0g = blockIdx.y * 128;
    const int n0g = blockIdx.x * 128;
    const int KT = K >> 4, MFR = Mp >> 4;

    const uint32_t* Wz;
    const __half* Xz;
    float* Yzf = nullptr; __half* Yzh = nullptr;
    const float* maa = nullptr; const __half2* xpb = nullptr;
    if (ACT == 4) {
        int s = z % 5, b = z / 5;
        Wz = Wp + (size_t)s * KT * MFR * 128;
        Xz = X + (size_t)b * 384 * Nn + (size_t)s * 64 * Nn;
        Yzh = (__half*)Yv + (size_t)(s * 8 + b) * sYz;
        maa = (s==0)?q0:(s==1)?q1:(s==2)?q2:(s==3)?q3:q4;
        xpb = g_xph + (size_t)b * Cc * Nn;
    } else {
        Wz = Wp + (size_t)(z % wmod) * KT * MFR * 128;
        Xz = X + (size_t)z * sXz;
        if (OUT == 0) Yzf = (float*)Yv + (size_t)z * sYz;
        else          Yzh = (__half*)Yv + (size_t)z * sYz;
    }

    __shared__ __align__(16) __half Bs[2][16][136];
    __shared__ __align__(16) uint4 As[2][256];           // 8 mfr x 512B per stage

    const int t = threadIdx.x;
    const int lane = t & 31, wid = t >> 5;
    const int wm = wid >> 2, wn = wid & 3;
    const int kRow = t >> 4, c8 = (t & 15) * 8;
    const int mfr0 = m0g >> 4;

    float acc[4][4][4];
    #pragma unroll
    for (int i = 0; i < 4; i++)
        #pragma unroll
        for (int jx = 0; jx < 4; jx++)
            #pragma unroll
            for (int q = 0; q < 4; q++) acc[i][jx][q] = 0.f;

    uint4 aPre, bRh;
    aPre = *(const uint4*)&Wz[((size_t)0 * MFR + mfr0) * 128 + t * 4];
    bRh  = *(const uint4*)&Xz[(size_t)kRow * Nn + n0g + c8];

    for (int kt = 0; kt < KT; kt++) {
        int buf = kt & 1;
        *(uint4*)&Bs[buf][kRow][c8] = bRh;
        As[buf][t] = aPre;
        __syncthreads();
        if (kt + 1 < KT) {
            aPre = *(const uint4*)&Wz[((size_t)(kt + 1) * MFR + mfr0) * 128 + t * 4];
            bRh  = *(const uint4*)&Xz[(size_t)((kt + 1) * 16 + kRow) * Nn + n0g + c8];
        }
        uint32_t abase = s2u(&As[buf][0]) + (uint32_t)(wm * 4) * 512 + lane * 16;
        uint4 af[4];
        #pragma unroll
        for (int mf = 0; mf < 4; mf++) ldmA(af[mf], abase + mf * 512);
        uint32_t base = s2u(&Bs[buf][lane & 15][wn * 32]);
        uint32_t bf[4][2];
        #pragma unroll
        for (int nf = 0; nf < 4; nf++) ldmB(bf[nf][0], bf[nf][1], base + nf * 16);
        #pragma unroll
        for (int mf = 0; mf < 4; mf++)
            #pragma unroll
            for (int nf = 0; nf < 4; nf++)
                mma16(acc[mf][nf], af[mf], bf[nf][0], bf[nf][1]);
        __syncthreads();
    }

    #pragma unroll
    for (int mf = 0; mf < 4; mf++) {
        int rr0 = m0g + wm * 64 + mf * 16 + (lane >> 2);
        #pragma unroll
        for (int hf = 0; hf < 2; hf++) {
            int rr = rr0 + hf * 8;
            float e  = (ACT == 3) ? extra[rr] : 0.f;
            float mc = (ACT == 4) ? maa[rr]   : 0.f;
            #pragma unroll
            for (int nf = 0; nf < 4; nf++) {
                int nc = n0g + wn * 32 + nf * 8 + (lane & 3) * 2;
                float v0 = acc[mf][nf][hf * 2 + 0];
                float v1 = acc[mf][nf][hf * 2 + 1];
                size_t off = (size_t)rr * Nn + nc;
                if (ACT == 1) { v0 = tanhf(v0); v1 = tanhf(v1); }
                else if (ACT == 2) { v0 = v0 / (1.f + expf(-v0)); v1 = v1 / (1.f + expf(-v1)); }
                else if (ACT == 3) { v0 = expf(-expf(e + v0)); v1 = expf(-expf(e + v1)); }
                else if (ACT == 4) {
                    uint2 xp = *(const uint2*)&xpb[off];
                    __half2 h0 = *(__half2*)&xp.x;       // {x0, xx0}
                    __half2 h1 = *(__half2*)&xp.y;       // {x1, xx1}
                    v0 = fmaf(__high2float(h0), mc + v0, __low2float(h0));
                    v1 = fmaf(__high2float(h1), mc + v1, __low2float(h1));
                }
                if (OUT == 0) {
                    *(float2*)&Yzf[off] = make_float2(v0, v1);
                } else {
                    __half2 h = __floats2half2_rn(v0, v1);
                    *(__half2*)&Yzh[off] = h;
                }
            }
        }
    }
}

// ---------------- K5: WKV6 scan, packed f32x2 (R12-proven) -------------------------
__global__ void __launch_bounds__(512) scan_kernel(const float* __restrict__ u_in) {
    const int bh = blockIdx.x;
    const int h = bh % 12, b = bh / 12;
    const int t = threadIdx.x;
    const int jq = t & 7, i = t >> 3;          // i = 0..63
    __shared__ __align__(16) float sm[4][2][16][68];   // comp r,k,d,v
    __shared__ __align__(16) float ytile[16][68];

    ull S2[4], u2[4], p2;
    #pragma unroll
    for (int p = 0; p < 4; p++) {
        S2[p] = 0ull;
        int j = 2 * jq + 16 * p;
        u2[p] = pk2(u_in[h * 64 + j], u_in[h * 64 + j + 1]);
    }

    const size_t cbase = ((size_t)b * 768 + h * 64) * 4096;
    const int csel = t >> 7, jldr = t & 63, nb = (t >> 6) & 1;
    const float* ap = (csel == 0) ? g_r : (csel == 1) ? g_k : (csel == 2) ? g_dec : g_v;
    const float* rowp = ap + cbase + (size_t)jldr * 4096;
    float* ydst = g_y + (size_t)b * 4096 * 768 + h * 64;

    float4 pre0 = *(const float4*)&rowp[nb * 4];
    float4 pre1 = *(const float4*)&rowp[(nb + 2) * 4];
    int cur = 0;
    for (int nt = 0; nt < 256; nt++) {
        {
            float* c0 = &sm[csel][cur][nb * 4][jldr];
            c0[0] = pre0.x; c0[68] = pre0.y; c0[136] = pre0.z; c0[204] = pre0.w;
            float* c1 = &sm[csel][cur][(nb + 2) * 4][jldr];
            c1[0] = pre1.x; c1[68] = pre1.y; c1[136] = pre1.z; c1[204] = pre1.w;
        }
        __syncthreads();
        if (nt + 1 < 256) {
            const float* np = rowp + (nt + 1) * 16;
            pre0 = *(const float4*)&np[nb * 4];
            pre1 = *(const float4*)&np[(nb + 2) * 4];
        }
        #pragma unroll
        for (int s = 0; s < 16; s++) {
            float v = sm[3][cur][s][i];
            ull v2 = pk2(v, v);
            p2 = 0ull;
            #pragma unroll
            for (int p = 0; p < 4; p++) {
                int j = 2 * jq + 16 * p;
                ull kk = *(const ull*)&sm[1][cur][s][j];
                ull dd = *(const ull*)&sm[2][cur][s][j];
                ull rr = *(const ull*)&sm[0][cur][s][j];
                ull kv = mul2(kk, v2);
                ull tmp = fma2(u2[p], kv, S2[p]);
                p2 = fma2(rr, tmp, p2);
                S2[p] = fma2(dd, S2[p], kv);
            }
            float plo, phi; upk2(plo, phi, p2);
            float pp = plo + phi;
            pp += __shfl_xor_sync(0xffffffffu, pp, 1);
            pp += __shfl_xor_sync(0xffffffffu, pp, 2);
            pp += __shfl_xor_sync(0xffffffffu, pp, 4);
            if (jq == 0) ytile[s][i] = pp;
        }
        __syncthreads();
        if (t < 256) {
            int tr = t >> 4, j4 = (t & 15) * 4;
            float4 o = *(float4*)&ytile[tr][j4];
            *(float4*)&ydst[(size_t)(nt * 16 + tr) * 768 + j4] = o;
        }
        cur ^= 1;
    }
}

// ---------------- K6: fused RMS + gate + transpose, fp16 channel-major out ---------
__global__ void __launch_bounds__(256) rmstgate_kernel(const float* __restrict__ lnw) {
    extern __shared__ float sy[];                 // [32][769]
    __shared__ float rmsv[32];
    const int t = threadIdx.x;
    const int tok0 = blockIdx.x * 32;
    const int b = tok0 >> 12, n0 = tok0 & 4095;
    const float* ybase = g_y + (size_t)tok0 * 768;

    #pragma unroll
    for (int it = 0; it < 24; it++) {
        int i = it * 256 + t;
        int tr = i / 192, c4 = i % 192;
        float4 v = *(const float4*)&ybase[(size_t)tr * 768 + c4 * 4];
        float* row = &sy[tr * 769];
        row[c4 * 4 + 0] = v.x; row[c4 * 4 + 1] = v.y;
        row[c4 * 4 + 2] = v.z; row[c4 * 4 + 3] = v.w;
    }
    __syncthreads();
    {
        int w = t >> 5, lane = t & 31;
        #pragma unroll
        for (int q = 0; q < 4; q++) {
            int tr = w * 4 + q;
            const float* row = &sy[tr * 769];
            float s = 0.f;
            #pragma unroll
            for (int jx = 0; jx < 24; jx++) { float v = row[lane + 32 * jx]; s += v * v; }
            #pragma unroll
            for (int off = 16; off; off >>= 1) s += __shfl_xor_sync(0xffffffffu, s, off);
            if (lane == 0) rmsv[tr] = rsqrtf(s * (1.f / 768.f) + 1e-6f);
        }
    }
    __syncthreads();
    #pragma unroll 4
    for (int it = 0; it < 96; it++) {
        int i = it * 256 + t;
        int c = i >> 5, tr = i & 31;
        float val = sy[tr * 769 + c];
        size_t go = ((size_t)(b * 768 + c)) * 4096 + n0 + tr;
        float g = __half2float(g_gateh[go]);
        g_y2h[go] = __float2half(val * rmsv[tr] * lnw[c] * g);
    }
}

// ---------------- launch ------------------------------------------------------------
extern "C" void kernel_launch(void* const* d_in, const int* in_sizes, int n_in,
                              void* d_out, int out_size) {
    const float* x        = (const float*)d_in[0];
    const float* maa_x    = (const float*)d_in[1];
    const float* maa_w    = (const float*)d_in[2];
    const float* maa_k    = (const float*)d_in[3];
    const float* maa_v    = (const float*)d_in[4];
    const float* maa_r    = (const float*)d_in[5];
    const float* maa_g    = (const float*)d_in[6];
    const float* maa_w1   = (const float*)d_in[7];
    const float* maa_w2   = (const float*)d_in[8];
    const float* tdecay   = (const float*)d_in[9];
    const float* td_w1    = (const float*)d_in[10];
    const float* td_w2    = (const float*)d_in[11];
    const float* faaaa    = (const float*)d_in[12];
    const float* key_w    = (const float*)d_in[13];
    const float* value_w  = (const float*)d_in[14];
    const float* recept_w = (const float*)d_in[15];
    const float* gate_w   = (const float*)d_in[16];
    const float* out_w    = (const float*)d_in[17];
    const float* ln_x_w   = (const float*)d_in[18];
    float* out = (float*)d_out;

    uint32_t *wh_t, *wh_w2, *wh_r, *wh_k, *wh_v, *wh_g, *wh_o, *wh_td1, *wh_td2;
    cudaGetSymbolAddress((void**)&wh_t,   g_wh_t);
    cudaGetSymbolAddress((void**)&wh_w2,  g_wh_w2);
    cudaGetSymbolAddress((void**)&wh_r,   g_wh_r);
    cudaGetSymbolAddress((void**)&wh_k,   g_wh_k);
    cudaGetSymbolAddress((void**)&wh_v,   g_wh_v);
    cudaGetSymbolAddress((void**)&wh_g,   g_wh_g);
    cudaGetSymbolAddress((void**)&wh_o,   g_wh_o);
    cudaGetSymbolAddress((void**)&wh_td1, g_wh_td1);
    cudaGetSymbolAddress((void**)&wh_td2, g_wh_td2);
    float *p_r, *p_k, *p_v, *p_dec;
    __half *p_xxxh, *p_th, *p_x5h, *p_gateh, *p_hh, *p_y2h;
    cudaGetSymbolAddress((void**)&p_xxxh, g_xxxh);
    cudaGetSymbolAddress((void**)&p_th,   g_th);
    cudaGetSymbolAddress((void**)&p_x5h,  g_x5h);
    cudaGetSymbolAddress((void**)&p_gateh,g_gateh);
    cudaGetSymbolAddress((void**)&p_hh,   g_hh);
    cudaGetSymbolAddress((void**)&p_y2h,  g_y2h);
    cudaGetSymbolAddress((void**)&p_r,    g_r);
    cudaGetSymbolAddress((void**)&p_k,    g_k);
    cudaGetSymbolAddress((void**)&p_v,    g_v);
    cudaGetSymbolAddress((void**)&p_dec,  g_dec);

    prep_all<<<4224, 256>>>(maa_w1, maa_w2, recept_w, key_w, value_w,
                            gate_w, out_w, td_w1, td_w2);

    shift_kernel<<<(BCN + 255) / 256, 256>>>(x, maa_x);

    #define NUL5 nullptr, nullptr, nullptr, nullptr, nullptr
    long long sC    = (long long)Cc * Nn;
    long long s384  = (long long)384 * Nn;
    long long s128  = (long long)128 * Nn;

    gemm_h<1,1><<<dim3(32, 3, 8), 256>>>(wh_t, p_xxxh, p_th, 384, 768, 1,
                                         sC, s384, nullptr, NUL5);

    gemm_h<4,1><<<dim3(32, 6, 40), 256>>>(wh_w2, p_th, p_x5h, 768, 64, 5,
                                          0, sC, nullptr,
                                          maa_w, maa_k, maa_v, maa_r, maa_g);

    gemm_h<0,0><<<dim3(32, 3, 16), 256>>>(wh_r, p_x5h + (size_t)3*BCN, p_r, 384, 384, 2,
                                          s384, s384, nullptr, NUL5);
    gemm_h<0,0><<<dim3(32, 3, 16), 256>>>(wh_k, p_x5h + (size_t)1*BCN, p_k, 384, 384, 2,
                                          s384, s384, nullptr, NUL5);
    gemm_h<0,0><<<dim3(32, 3, 16), 256>>>(wh_v, p_x5h + (size_t)2*BCN, p_v, 384, 384, 2,
                                          s384, s384, nullptr, NUL5);
    gemm_h<2,1><<<dim3(32, 3, 16), 256>>>(wh_g, p_x5h + (size_t)4*BCN, p_gateh, 384, 384, 2,
                                          s384, s384, nullptr, NUL5);

    gemm_h<1,1><<<dim3(32, 1, 8), 256>>>(wh_td1, p_x5h, p_hh, 128, 768, 1,
                                         sC, s128, nullptr, NUL5);
    gemm_h<3,0><<<dim3(32, 6, 8), 256>>>(wh_td2, p_hh, p_dec, 768, 64, 1,
                                         s128, sC, tdecay, NUL5);

    scan_kernel<<<96, 512>>>(faaaa);

    cudaFuncSetAttribute(rmstgate_kernel, cudaFuncAttributeMaxDynamicSharedMemorySize,
                         32 * 769 * 4);
    rmstgate_kernel<<<TOK / 32, 256, 32 * 769 * 4>>>(ln_x_w);

    gemm_h<0,0><<<dim3(32, 3, 16), 256>>>(wh_o, p_y2h, out, 384, 384, 2,
                                          s384, s384, nullptr, NUL5);
}